// round 4
// baseline (speedup 1.0000x reference)
#include <cuda_runtime.h>
#include <cuda_bf16.h>
#include <cstdint>

#define D_MODEL 2048
#define HIDDEN 1024
#define NUM_EXPERTS 8
#define TPE 2048
#define TOTAL_TOKENS 16384

// fp32 scratch for h = silu(gate)*up : [16384, 1024]
__device__ float g_h[(size_t)TOTAL_TOKENS * HIDDEN];

// ---------------- helpers ----------------
__device__ __forceinline__ uint32_t sw(uint32_t off) {
    // rows are 64B (32 bf16); XOR bits[5:4] with bits[8:7] -> conflict-free
    return off ^ ((off >> 3) & 0x30);
}

__device__ __forceinline__ uint32_t smem_u32(const void* p) {
    return (uint32_t)__cvta_generic_to_shared(p);
}

__device__ __forceinline__ void mma_bf16(float* c, const uint32_t* a,
                                         uint32_t b0, uint32_t b1) {
    asm volatile(
        "mma.sync.aligned.m16n8k16.row.col.f32.bf16.bf16.f32 "
        "{%0,%1,%2,%3}, {%4,%5,%6,%7}, {%8,%9}, {%0,%1,%2,%3};"
        : "+f"(c[0]), "+f"(c[1]), "+f"(c[2]), "+f"(c[3])
        : "r"(a[0]), "r"(a[1]), "r"(a[2]), "r"(a[3]), "r"(b0), "r"(b1));
}

__device__ __forceinline__ void ldsm4(uint32_t r[4], uint32_t saddr) {
    asm volatile("ldmatrix.sync.aligned.m8n8.x4.shared.b16 {%0,%1,%2,%3}, [%4];"
                 : "=r"(r[0]), "=r"(r[1]), "=r"(r[2]), "=r"(r[3]) : "r"(saddr));
}

__device__ __forceinline__ uint32_t pack_bf16x2(float lo_f, float hi_f) {
    __nv_bfloat162 p(__float2bfloat16(lo_f), __float2bfloat16(hi_f));
    return *reinterpret_cast<uint32_t*>(&p);
}

// split float4 (4 consecutive K values) into hi/lo packed pairs
__device__ __forceinline__ void split4(float4 v, uint2& hv, uint2& lv) {
    float hx = __bfloat162float(__float2bfloat16(v.x));
    float hy = __bfloat162float(__float2bfloat16(v.y));
    float hz = __bfloat162float(__float2bfloat16(v.z));
    float hw = __bfloat162float(__float2bfloat16(v.w));
    hv.x = pack_bf16x2(v.x, v.y);
    hv.y = pack_bf16x2(v.z, v.w);
    lv.x = pack_bf16x2(v.x - hx, v.y - hy);
    lv.y = pack_bf16x2(v.z - hz, v.w - hw);
}

// SMEM stage layout (bytes): Ahi 0, Alo 8192, Bhi 16384, Blo 24576; stage = 32768
#define TILE8K 8192
#define STAGE 32768

// store one 128x32 fp32 tile (4 float4/thread in regs) as bf16 hi/lo
__device__ __forceinline__ void sts_tile(char* dhi, char* dlo, const float4* r, int tid) {
    #pragma unroll
    for (int it = 0; it < 4; it++) {
        int idx = it * 256 + tid;
        int row = idx >> 3;            // 0..127
        int c4  = idx & 7;             // float4 within 32-col row
        uint2 hv, lv;
        split4(r[it], hv, lv);
        uint32_t off = sw((uint32_t)(row * 64 + c4 * 8));
        *reinterpret_cast<uint2*>(dhi + off) = hv;
        *reinterpret_cast<uint2*>(dlo + off) = lv;
    }
}

// compute one 32-K chunk: frags loaded ONCE per k16 via ldmatrix, reused
// across 3 passes (hi*hi, hi*lo, lo*hi).
__device__ __forceinline__ void compute_chunk(uint32_t st, float acc[4][4][4],
                                              int lane, int mw, int nw) {
    const uint32_t Ahi = st, Alo = st + TILE8K;
    const uint32_t Bhi = st + 2 * TILE8K, Blo = st + 3 * TILE8K;
    const int lrow = lane & 15;
    const uint32_t lhi = (uint32_t)(lane >> 4) * 16;

    #pragma unroll
    for (int ks = 0; ks < 2; ks++) {
        const uint32_t kc = (uint32_t)ks * 32 + lhi;
        uint32_t ah[4][4], al[4][4], bh[2][4], bl[2][4];

        #pragma unroll
        for (int mt = 0; mt < 4; mt++) {
            uint32_t R = (uint32_t)(mw * 64 + mt * 16 + lrow) * 64;
            uint32_t off = R + (kc ^ ((R >> 3) & 0x30));
            ldsm4(ah[mt], Ahi + off);
            ldsm4(al[mt], Alo + off);
        }
        #pragma unroll
        for (int pr = 0; pr < 2; pr++) {
            uint32_t R = (uint32_t)(nw * 32 + pr * 16 + lrow) * 64;
            uint32_t off = R + (kc ^ ((R >> 3) & 0x30));
            ldsm4(bh[pr], Bhi + off);
            ldsm4(bl[pr], Blo + off);
        }

        // pass 0: Ahi x Bhi
        #pragma unroll
        for (int mt = 0; mt < 4; mt++)
            #pragma unroll
            for (int nt = 0; nt < 4; nt++)
                mma_bf16(acc[mt][nt], ah[mt], bh[nt >> 1][nt & 1], bh[nt >> 1][(nt & 1) + 2]);
        // pass 1: Ahi x Blo
        #pragma unroll
        for (int mt = 0; mt < 4; mt++)
            #pragma unroll
            for (int nt = 0; nt < 4; nt++)
                mma_bf16(acc[mt][nt], ah[mt], bl[nt >> 1][nt & 1], bl[nt >> 1][(nt & 1) + 2]);
        // pass 2: Alo x Bhi
        #pragma unroll
        for (int mt = 0; mt < 4; mt++)
            #pragma unroll
            for (int nt = 0; nt < 4; nt++)
                mma_bf16(acc[mt][nt], al[mt], bh[nt >> 1][nt & 1], bh[nt >> 1][(nt & 1) + 2]);
    }
}

__device__ __forceinline__ float silu(float x) {
    return x / (1.0f + __expf(-x));
}

// ---------------- kernel 1: h = silu(x@Wg^T) * (x@Wu^T), fused ----------------
// CTA: 128 tokens x 64 h-cols. B-tile (128 rows) interleaves gate/up per 16 rows
// so every warp (64x32 B-tile) holds matching gate/up columns for fusion.
__global__ __launch_bounds__(256, 1)
void moe_upgate_kernel(const float* __restrict__ x,
                       const float* __restrict__ w_upgate,
                       float* __restrict__ h_out)
{
    extern __shared__ char smem[];
    const uint32_t smem_b = smem_u32(smem);

    const int tid = threadIdx.x;
    const int lane = tid & 31, warp = tid >> 5;
    const int g = lane >> 2, tg = lane & 3;
    const int nw = warp & 3, mw = warp >> 2;

    const int e = blockIdx.z;
    const int m0 = blockIdx.y * 128;
    const int n0 = blockIdx.x * 64;

    const float* A  = x + (long)e * TPE * D_MODEL + (long)m0 * D_MODEL;
    const float* Bg = w_upgate + (long)e * 2 * HIDDEN * D_MODEL;
    const float* Bu = Bg + (long)HIDDEN * D_MODEL;

    const int lrow = tid >> 3;
    const int lc4  = tid & 7;

    float acc[4][4][4];
    #pragma unroll
    for (int i = 0; i < 4; i++)
        #pragma unroll
        for (int j = 0; j < 4; j++)
            #pragma unroll
            for (int k = 0; k < 4; k++) acc[i][j][k] = 0.0f;

    float4 ra[4], rb[4];

    auto ldg = [&](int k0) {
        #pragma unroll
        for (int it = 0; it < 4; it++) {
            int r = it * 32 + lrow;
            ra[it] = *reinterpret_cast<const float4*>(A + (long)r * D_MODEL + k0 + lc4 * 4);
            int w = r >> 5, s = (r >> 4) & 1, rr = (r & 15) + w * 16;
            const float* bp = s ? Bu : Bg;
            rb[it] = *reinterpret_cast<const float4*>(bp + (long)(n0 + rr) * D_MODEL + k0 + lc4 * 4);
        }
    };

    const int NCH = D_MODEL / 32;   // 64
    ldg(0);
    sts_tile(smem, smem + TILE8K, ra, tid);
    sts_tile(smem + 2 * TILE8K, smem + 3 * TILE8K, rb, tid);

    for (int c = 0; c < NCH; c++) {
        __syncthreads();
        if (c + 1 < NCH) ldg((c + 1) * 32);
        compute_chunk(smem_b + (c & 1) * STAGE, acc, lane, mw, nw);
        if (c + 1 < NCH) {
            char* st = smem + ((c + 1) & 1) * STAGE;
            sts_tile(st, st + TILE8K, ra, tid);
            sts_tile(st + 2 * TILE8K, st + 3 * TILE8K, rb, tid);
        }
    }

    // epilogue: nt 0,1 = gate cols, nt 2,3 = matching up cols
    #pragma unroll
    for (int mt = 0; mt < 4; mt++) {
        long row0 = (long)e * TPE + m0 + mw * 64 + mt * 16 + g;
        #pragma unroll
        for (int nt = 0; nt < 2; nt++) {
            int col = n0 + nw * 16 + nt * 8 + tg * 2;
            float2 v0, v1;
            v0.x = silu(acc[mt][nt][0]) * acc[mt][nt + 2][0];
            v0.y = silu(acc[mt][nt][1]) * acc[mt][nt + 2][1];
            v1.x = silu(acc[mt][nt][2]) * acc[mt][nt + 2][2];
            v1.y = silu(acc[mt][nt][3]) * acc[mt][nt + 2][3];
            *reinterpret_cast<float2*>(g_h + row0 * HIDDEN + col) = v0;
            *reinterpret_cast<float2*>(g_h + (row0 + 8) * HIDDEN + col) = v1;
        }
    }
}

// ---------------- kernel 2: out = h @ Wd^T ----------------
__global__ __launch_bounds__(256, 1)
void moe_down_kernel(const float* __restrict__ w_down,
                     float* __restrict__ out)
{
    extern __shared__ char smem[];
    const uint32_t smem_b = smem_u32(smem);

    const int tid = threadIdx.x;
    const int lane = tid & 31, warp = tid >> 5;
    const int g = lane >> 2, tg = lane & 3;
    const int nw = warp & 3, mw = warp >> 2;

    const int e = blockIdx.z;
    const int m0 = blockIdx.y * 128;
    const int n0 = blockIdx.x * 128;

    const float* A = g_h + (long)e * TPE * HIDDEN + (long)m0 * HIDDEN;
    const float* B = w_down + (long)n0 * (NUM_EXPERTS * HIDDEN) + (long)e * HIDDEN;

    const int lrow = tid >> 3;
    const int lc4  = tid & 7;

    float acc[4][4][4];
    #pragma unroll
    for (int i = 0; i < 4; i++)
        #pragma unroll
        for (int j = 0; j < 4; j++)
            #pragma unroll
            for (int k = 0; k < 4; k++) acc[i][j][k] = 0.0f;

    float4 ra[4], rb[4];

    auto ldg = [&](int k0) {
        #pragma unroll
        for (int it = 0; it < 4; it++) {
            int r = it * 32 + lrow;
            ra[it] = *reinterpret_cast<const float4*>(A + (long)r * HIDDEN + k0 + lc4 * 4);
            rb[it] = *reinterpret_cast<const float4*>(B + (long)r * (NUM_EXPERTS * HIDDEN) + k0 + lc4 * 4);
        }
    };

    const int NCH = HIDDEN / 32;    // 32
    ldg(0);
    sts_tile(smem, smem + TILE8K, ra, tid);
    sts_tile(smem + 2 * TILE8K, smem + 3 * TILE8K, rb, tid);

    for (int c = 0; c < NCH; c++) {
        __syncthreads();
        if (c + 1 < NCH) ldg((c + 1) * 32);
        compute_chunk(smem_b + (c & 1) * STAGE, acc, lane, mw, nw);
        if (c + 1 < NCH) {
            char* st = smem + ((c + 1) & 1) * STAGE;
            sts_tile(st, st + TILE8K, ra, tid);
            sts_tile(st + 2 * TILE8K, st + 3 * TILE8K, rb, tid);
        }
    }

    #pragma unroll
    for (int mt = 0; mt < 4; mt++) {
        long row0 = (long)e * TPE + m0 + mw * 64 + mt * 16 + g;
        #pragma unroll
        for (int nt = 0; nt < 4; nt++) {
            int col = n0 + nw * 32 + nt * 8 + tg * 2;
            float2 v0, v1;
            v0.x = acc[mt][nt][0]; v0.y = acc[mt][nt][1];
            v1.x = acc[mt][nt][2]; v1.y = acc[mt][nt][3];
            *reinterpret_cast<float2*>(out + row0 * D_MODEL + col) = v0;
            *reinterpret_cast<float2*>(out + (row0 + 8) * D_MODEL + col) = v1;
        }
    }
}

// ---------------- launch ----------------
extern "C" void kernel_launch(void* const* d_in, const int* in_sizes, int n_in,
                              void* d_out, int out_size)
{
    const float* x        = (const float*)d_in[0];  // [16384, 2048]
    const float* w_upgate = (const float*)d_in[1];  // [E*2H, D]
    const float* w_down   = (const float*)d_in[2];  // [D, E*H]
    float* out = (float*)d_out;

    cudaFuncSetAttribute(moe_upgate_kernel,
                         cudaFuncAttributeMaxDynamicSharedMemorySize, 2 * STAGE);
    cudaFuncSetAttribute(moe_down_kernel,
                         cudaFuncAttributeMaxDynamicSharedMemorySize, 2 * STAGE);

    float* hptr;
    cudaGetSymbolAddress((void**)&hptr, g_h);

    {
        dim3 grid(HIDDEN / 64, TPE / 128, NUM_EXPERTS);   // (16,16,8)
        moe_upgate_kernel<<<grid, 256, 2 * STAGE>>>(x, w_upgate, hptr);
    }
    {
        dim3 grid(D_MODEL / 128, TPE / 128, NUM_EXPERTS); // (16,16,8)
        moe_down_kernel<<<grid, 256, 2 * STAGE>>>(w_down, out);
    }
}

// round 5
// speedup vs baseline: 1.0028x; 1.0028x over previous
#include <cuda_runtime.h>
#include <cuda_bf16.h>
#include <cstdint>

#define D_MODEL 2048
#define HIDDEN 1024
#define NUM_EXPERTS 8
#define TPE 2048
#define TOTAL_TOKENS 16384

// bf16 hi/lo pre-split copies (written once per launch by split kernels)
__device__ __nv_bfloat16 g_x_hi[(size_t)TOTAL_TOKENS * D_MODEL];
__device__ __nv_bfloat16 g_x_lo[(size_t)TOTAL_TOKENS * D_MODEL];
__device__ __nv_bfloat16 g_wug_hi[(size_t)2 * NUM_EXPERTS * HIDDEN * D_MODEL];
__device__ __nv_bfloat16 g_wug_lo[(size_t)2 * NUM_EXPERTS * HIDDEN * D_MODEL];
__device__ __nv_bfloat16 g_wd_hi[(size_t)D_MODEL * NUM_EXPERTS * HIDDEN];
__device__ __nv_bfloat16 g_wd_lo[(size_t)D_MODEL * NUM_EXPERTS * HIDDEN];
__device__ __nv_bfloat16 g_h_hi[(size_t)TOTAL_TOKENS * HIDDEN];
__device__ __nv_bfloat16 g_h_lo[(size_t)TOTAL_TOKENS * HIDDEN];

// ---------------- helpers ----------------
__device__ __forceinline__ uint32_t sw(uint32_t off) {
    // rows are 64B (32 bf16); XOR bits[5:4] with bits[8:7] -> conflict-free
    return off ^ ((off >> 3) & 0x30);
}

__device__ __forceinline__ uint32_t smem_u32(const void* p) {
    return (uint32_t)__cvta_generic_to_shared(p);
}

__device__ __forceinline__ void mma_bf16(float* c, const uint32_t* a,
                                         uint32_t b0, uint32_t b1) {
    asm volatile(
        "mma.sync.aligned.m16n8k16.row.col.f32.bf16.bf16.f32 "
        "{%0,%1,%2,%3}, {%4,%5,%6,%7}, {%8,%9}, {%0,%1,%2,%3};"
        : "+f"(c[0]), "+f"(c[1]), "+f"(c[2]), "+f"(c[3])
        : "r"(a[0]), "r"(a[1]), "r"(a[2]), "r"(a[3]), "r"(b0), "r"(b1));
}

__device__ __forceinline__ void ldsm4(uint32_t r[4], uint32_t saddr) {
    asm volatile("ldmatrix.sync.aligned.m8n8.x4.shared.b16 {%0,%1,%2,%3}, [%4];"
                 : "=r"(r[0]), "=r"(r[1]), "=r"(r[2]), "=r"(r[3]) : "r"(saddr));
}

#define CP_ASYNC16(dst, src) \
    asm volatile("cp.async.cg.shared.global [%0], [%1], 16;" :: "r"(dst), "l"(src))
#define CP_COMMIT() asm volatile("cp.async.commit_group;" ::: "memory")
#define CP_WAIT1()  asm volatile("cp.async.wait_group 1;" ::: "memory")

__device__ __forceinline__ uint32_t pack_bf16x2(float lo_f, float hi_f) {
    __nv_bfloat162 p(__float2bfloat16(lo_f), __float2bfloat16(hi_f));
    return *reinterpret_cast<uint32_t*>(&p);
}

__device__ __forceinline__ void split4(float4 v, uint2& hv, uint2& lv) {
    float hx = __bfloat162float(__float2bfloat16(v.x));
    float hy = __bfloat162float(__float2bfloat16(v.y));
    float hz = __bfloat162float(__float2bfloat16(v.z));
    float hw = __bfloat162float(__float2bfloat16(v.w));
    hv.x = pack_bf16x2(v.x, v.y);
    hv.y = pack_bf16x2(v.z, v.w);
    lv.x = pack_bf16x2(v.x - hx, v.y - hy);
    lv.y = pack_bf16x2(v.z - hz, v.w - hw);
}

// SMEM stage: Ahi 0, Alo 8K, Bhi 16K, Blo 24K; 3 stages
#define TILE8K 8192
#define STAGE 32768
#define NSTAGE 3

// compute one 32-K chunk: frags via ldmatrix, reused across 3 passes
__device__ __forceinline__ void compute_chunk(uint32_t st, float acc[4][4][4],
                                              int lane, int mw, int nw) {
    const uint32_t Ahi = st, Alo = st + TILE8K;
    const uint32_t Bhi = st + 2 * TILE8K, Blo = st + 3 * TILE8K;
    const int lrow = lane & 15;
    const uint32_t lhi = (uint32_t)(lane >> 4) * 16;

    #pragma unroll
    for (int ks = 0; ks < 2; ks++) {
        const uint32_t kc = (uint32_t)ks * 32 + lhi;
        uint32_t ah[4][4], al[4][4], bh[2][4], bl[2][4];

        #pragma unroll
        for (int mt = 0; mt < 4; mt++) {
            uint32_t R = (uint32_t)(mw * 64 + mt * 16 + lrow) * 64;
            uint32_t off = R + (kc ^ ((R >> 3) & 0x30));
            ldsm4(ah[mt], Ahi + off);
            ldsm4(al[mt], Alo + off);
        }
        #pragma unroll
        for (int pr = 0; pr < 2; pr++) {
            uint32_t R = (uint32_t)(nw * 32 + pr * 16 + lrow) * 64;
            uint32_t off = R + (kc ^ ((R >> 3) & 0x30));
            ldsm4(bh[pr], Bhi + off);
            ldsm4(bl[pr], Blo + off);
        }

        #pragma unroll
        for (int mt = 0; mt < 4; mt++)
            #pragma unroll
            for (int nt = 0; nt < 4; nt++)
                mma_bf16(acc[mt][nt], ah[mt], bh[nt >> 1][nt & 1], bh[nt >> 1][(nt & 1) + 2]);
        #pragma unroll
        for (int mt = 0; mt < 4; mt++)
            #pragma unroll
            for (int nt = 0; nt < 4; nt++)
                mma_bf16(acc[mt][nt], ah[mt], bl[nt >> 1][nt & 1], bl[nt >> 1][(nt & 1) + 2]);
        #pragma unroll
        for (int mt = 0; mt < 4; mt++)
            #pragma unroll
            for (int nt = 0; nt < 4; nt++)
                mma_bf16(acc[mt][nt], al[mt], bh[nt >> 1][nt & 1], bh[nt >> 1][(nt & 1) + 2]);
    }
}

__device__ __forceinline__ float silu(float x) {
    return x / (1.0f + __expf(-x));
}

// ---------------- split kernel: fp32 -> bf16 hi/lo ----------------
__global__ void split_kernel(const float4* __restrict__ src,
                             uint2* __restrict__ hi, uint2* __restrict__ lo, long n4)
{
    for (long i = (long)blockIdx.x * blockDim.x + threadIdx.x; i < n4;
         i += (long)gridDim.x * blockDim.x) {
        uint2 h, l;
        split4(src[i], h, l);
        hi[i] = h;
        lo[i] = l;
    }
}

// ---------------- kernel 1: h = silu(x@Wg^T) * (x@Wu^T), fused ----------------
// CTA: 128 tokens x 64 h-cols; B~ tile (128 rows) interleaves gate/up per 16 rows.
__global__ __launch_bounds__(256, 1)
void moe_upgate_kernel()
{
    extern __shared__ char smem[];
    const uint32_t smem_b = smem_u32(smem);

    const int tid = threadIdx.x;
    const int lane = tid & 31, warp = tid >> 5;
    const int g = lane >> 2, tg = lane & 3;
    const int nw = warp & 3, mw = warp >> 2;

    const int e = blockIdx.z;
    const int m0 = blockIdx.y * 128;
    const int n0 = blockIdx.x * 64;

    const long arow0 = (long)e * TPE + m0;       // token row base
    const long brow0 = (long)e * 2 * HIDDEN;     // wug row base for expert

    // per-thread cp.async coords: 2 iters x (row = idx>>2, 16B chunk = idx&3)
    auto issue_stage = [&](int s, int c) {
        const int k0 = c * 32;
        const uint32_t st = smem_b + (uint32_t)s * STAGE;
        #pragma unroll
        for (int it = 0; it < 2; it++) {
            int idx = it * 256 + tid;
            int row = idx >> 2, c16 = idx & 3;
            uint32_t off = sw((uint32_t)(row * 64 + c16 * 16));
            long acol = (long)k0 + c16 * 8;
            const __nv_bfloat16* a_hi = g_x_hi + (arow0 + row) * D_MODEL + acol;
            const __nv_bfloat16* a_lo = g_x_lo + (arow0 + row) * D_MODEL + acol;
            int w = row >> 5, sgu = (row >> 4) & 1, rr = (row & 15) + w * 16;
            long brow = brow0 + (sgu ? HIDDEN : 0) + n0 + rr;
            const __nv_bfloat16* b_hi = g_wug_hi + brow * D_MODEL + acol;
            const __nv_bfloat16* b_lo = g_wug_lo + brow * D_MODEL + acol;
            CP_ASYNC16(st + off, a_hi);
            CP_ASYNC16(st + TILE8K + off, a_lo);
            CP_ASYNC16(st + 2 * TILE8K + off, b_hi);
            CP_ASYNC16(st + 3 * TILE8K + off, b_lo);
        }
        CP_COMMIT();
    };

    float acc[4][4][4];
    #pragma unroll
    for (int i = 0; i < 4; i++)
        #pragma unroll
        for (int j = 0; j < 4; j++)
            #pragma unroll
            for (int k = 0; k < 4; k++) acc[i][j][k] = 0.0f;

    const int NCH = D_MODEL / 32;   // 64
    issue_stage(0, 0);
    issue_stage(1, 1);

    for (int c = 0; c < NCH; c++) {
        CP_WAIT1();
        __syncthreads();
        if (c + 2 < NCH) issue_stage((c + 2) % NSTAGE, c + 2);
        else CP_COMMIT();
        compute_chunk(smem_b + (uint32_t)(c % NSTAGE) * STAGE, acc, lane, mw, nw);
    }

    // epilogue: nt 0,1 = gate, nt 2,3 = matching up; write h as bf16 hi/lo
    #pragma unroll
    for (int mt = 0; mt < 4; mt++) {
        long row0 = arow0 + mw * 64 + mt * 16 + g;
        #pragma unroll
        for (int nt = 0; nt < 2; nt++) {
            int col = n0 + nw * 16 + nt * 8 + tg * 2;
            float vx = silu(acc[mt][nt][0]) * acc[mt][nt + 2][0];
            float vy = silu(acc[mt][nt][1]) * acc[mt][nt + 2][1];
            float vz = silu(acc[mt][nt][2]) * acc[mt][nt + 2][2];
            float vw = silu(acc[mt][nt][3]) * acc[mt][nt + 2][3];
            float hx = __bfloat162float(__float2bfloat16(vx));
            float hy = __bfloat162float(__float2bfloat16(vy));
            float hz = __bfloat162float(__float2bfloat16(vz));
            float hw = __bfloat162float(__float2bfloat16(vw));
            *reinterpret_cast<uint32_t*>(g_h_hi + row0 * HIDDEN + col) = pack_bf16x2(vx, vy);
            *reinterpret_cast<uint32_t*>(g_h_lo + row0 * HIDDEN + col) = pack_bf16x2(vx - hx, vy - hy);
            *reinterpret_cast<uint32_t*>(g_h_hi + (row0 + 8) * HIDDEN + col) = pack_bf16x2(vz, vw);
            *reinterpret_cast<uint32_t*>(g_h_lo + (row0 + 8) * HIDDEN + col) = pack_bf16x2(vz - hz, vw - hw);
        }
    }
}

// ---------------- kernel 2: out = h @ Wd^T ----------------
__global__ __launch_bounds__(256, 1)
void moe_down_kernel(float* __restrict__ out)
{
    extern __shared__ char smem[];
    const uint32_t smem_b = smem_u32(smem);

    const int tid = threadIdx.x;
    const int lane = tid & 31, warp = tid >> 5;
    const int g = lane >> 2, tg = lane & 3;
    const int nw = warp & 3, mw = warp >> 2;

    const int e = blockIdx.z;
    const int m0 = blockIdx.y * 128;
    const int n0 = blockIdx.x * 128;

    const long arow0 = (long)e * TPE + m0;
    const long bcol0 = (long)e * HIDDEN;

    auto issue_stage = [&](int s, int c) {
        const int k0 = c * 32;
        const uint32_t st = smem_b + (uint32_t)s * STAGE;
        #pragma unroll
        for (int it = 0; it < 2; it++) {
            int idx = it * 256 + tid;
            int row = idx >> 2, c16 = idx & 3;
            uint32_t off = sw((uint32_t)(row * 64 + c16 * 16));
            long acol = (long)k0 + c16 * 8;
            const __nv_bfloat16* a_hi = g_h_hi + (arow0 + row) * HIDDEN + acol;
            const __nv_bfloat16* a_lo = g_h_lo + (arow0 + row) * HIDDEN + acol;
            const __nv_bfloat16* b_hi = g_wd_hi + (long)(n0 + row) * (NUM_EXPERTS * HIDDEN) + bcol0 + acol;
            const __nv_bfloat16* b_lo = g_wd_lo + (long)(n0 + row) * (NUM_EXPERTS * HIDDEN) + bcol0 + acol;
            CP_ASYNC16(st + off, a_hi);
            CP_ASYNC16(st + TILE8K + off, a_lo);
            CP_ASYNC16(st + 2 * TILE8K + off, b_hi);
            CP_ASYNC16(st + 3 * TILE8K + off, b_lo);
        }
        CP_COMMIT();
    };

    float acc[4][4][4];
    #pragma unroll
    for (int i = 0; i < 4; i++)
        #pragma unroll
        for (int j = 0; j < 4; j++)
            #pragma unroll
            for (int k = 0; k < 4; k++) acc[i][j][k] = 0.0f;

    const int NCH = HIDDEN / 32;    // 32
    issue_stage(0, 0);
    issue_stage(1, 1);

    for (int c = 0; c < NCH; c++) {
        CP_WAIT1();
        __syncthreads();
        if (c + 2 < NCH) issue_stage((c + 2) % NSTAGE, c + 2);
        else CP_COMMIT();
        compute_chunk(smem_b + (uint32_t)(c % NSTAGE) * STAGE, acc, lane, mw, nw);
    }

    #pragma unroll
    for (int mt = 0; mt < 4; mt++) {
        long row0 = arow0 + mw * 64 + mt * 16 + g;
        #pragma unroll
        for (int nt = 0; nt < 4; nt++) {
            int col = n0 + nw * 32 + nt * 8 + tg * 2;
            float2 v0, v1;
            v0.x = acc[mt][nt][0]; v0.y = acc[mt][nt][1];
            v1.x = acc[mt][nt][2]; v1.y = acc[mt][nt][3];
            *reinterpret_cast<float2*>(out + row0 * D_MODEL + col) = v0;
            *reinterpret_cast<float2*>(out + (row0 + 8) * D_MODEL + col) = v1;
        }
    }
}

// ---------------- launch ----------------
extern "C" void kernel_launch(void* const* d_in, const int* in_sizes, int n_in,
                              void* d_out, int out_size)
{
    const float* x        = (const float*)d_in[0];  // [16384, 2048]
    const float* w_upgate = (const float*)d_in[1];  // [E*2H, D]
    const float* w_down   = (const float*)d_in[2];  // [D, E*H]
    float* out = (float*)d_out;

    cudaFuncSetAttribute(moe_upgate_kernel,
                         cudaFuncAttributeMaxDynamicSharedMemorySize, NSTAGE * STAGE);
    cudaFuncSetAttribute(moe_down_kernel,
                         cudaFuncAttributeMaxDynamicSharedMemorySize, NSTAGE * STAGE);

    __nv_bfloat16 *xh, *xl, *ugh, *ugl, *wdh, *wdl;
    cudaGetSymbolAddress((void**)&xh,  g_x_hi);
    cudaGetSymbolAddress((void**)&xl,  g_x_lo);
    cudaGetSymbolAddress((void**)&ugh, g_wug_hi);
    cudaGetSymbolAddress((void**)&ugl, g_wug_lo);
    cudaGetSymbolAddress((void**)&wdh, g_wd_hi);
    cudaGetSymbolAddress((void**)&wdl, g_wd_lo);

    // split fp32 -> bf16 hi/lo
    {
        long n4x  = (long)TOTAL_TOKENS * D_MODEL / 4;
        long n4ug = (long)2 * NUM_EXPERTS * HIDDEN * D_MODEL / 4;
        long n4wd = (long)D_MODEL * NUM_EXPERTS * HIDDEN / 4;
        split_kernel<<<2048, 256>>>((const float4*)x, (uint2*)xh, (uint2*)xl, n4x);
        split_kernel<<<2048, 256>>>((const float4*)w_upgate, (uint2*)ugh, (uint2*)ugl, n4ug);
        split_kernel<<<2048, 256>>>((const float4*)w_down, (uint2*)wdh, (uint2*)wdl, n4wd);
    }

    {
        dim3 grid(HIDDEN / 64, TPE / 128, NUM_EXPERTS);   // (16,16,8)
        moe_upgate_kernel<<<grid, 256, NSTAGE * STAGE>>>();
    }
    {
        dim3 grid(D_MODEL / 128, TPE / 128, NUM_EXPERTS); // (16,16,8)
        moe_down_kernel<<<grid, 256, NSTAGE * STAGE>>>(out);
    }
}

// round 6
// speedup vs baseline: 1.0829x; 1.0799x over previous
#include <cuda_runtime.h>
#include <cuda_bf16.h>
#include <cstdint>

#define D_MODEL 2048
#define HIDDEN 1024
#define NUM_EXPERTS 8
#define TPE 2048
#define TOTAL_TOKENS 16384

// bf16 hi/lo pre-split copies (written once per launch by split kernels)
__device__ __nv_bfloat16 g_x_hi[(size_t)TOTAL_TOKENS * D_MODEL];
__device__ __nv_bfloat16 g_x_lo[(size_t)TOTAL_TOKENS * D_MODEL];
__device__ __nv_bfloat16 g_wug_hi[(size_t)2 * NUM_EXPERTS * HIDDEN * D_MODEL];
__device__ __nv_bfloat16 g_wug_lo[(size_t)2 * NUM_EXPERTS * HIDDEN * D_MODEL];
__device__ __nv_bfloat16 g_wd_hi[(size_t)D_MODEL * NUM_EXPERTS * HIDDEN];
__device__ __nv_bfloat16 g_wd_lo[(size_t)D_MODEL * NUM_EXPERTS * HIDDEN];
__device__ __nv_bfloat16 g_h_hi[(size_t)TOTAL_TOKENS * HIDDEN];
__device__ __nv_bfloat16 g_h_lo[(size_t)TOTAL_TOKENS * HIDDEN];

// ---------------- helpers ----------------
__device__ __forceinline__ uint32_t sw(uint32_t off) {
    // rows are 64B (32 bf16); XOR bits[5:4] with bits[8:7] -> conflict-free
    return off ^ ((off >> 3) & 0x30);
}

__device__ __forceinline__ uint32_t smem_u32(const void* p) {
    return (uint32_t)__cvta_generic_to_shared(p);
}

__device__ __forceinline__ void mma_bf16(float* c, const uint32_t* a,
                                         uint32_t b0, uint32_t b1) {
    asm volatile(
        "mma.sync.aligned.m16n8k16.row.col.f32.bf16.bf16.f32 "
        "{%0,%1,%2,%3}, {%4,%5,%6,%7}, {%8,%9}, {%0,%1,%2,%3};"
        : "+f"(c[0]), "+f"(c[1]), "+f"(c[2]), "+f"(c[3])
        : "r"(a[0]), "r"(a[1]), "r"(a[2]), "r"(a[3]), "r"(b0), "r"(b1));
}

__device__ __forceinline__ void ldsm4(uint32_t r[4], uint32_t saddr) {
    asm volatile("ldmatrix.sync.aligned.m8n8.x4.shared.b16 {%0,%1,%2,%3}, [%4];"
                 : "=r"(r[0]), "=r"(r[1]), "=r"(r[2]), "=r"(r[3]) : "r"(saddr));
}

#define CP_ASYNC16(dst, src) \
    asm volatile("cp.async.cg.shared.global [%0], [%1], 16;" :: "r"(dst), "l"(src))
#define CP_COMMIT() asm volatile("cp.async.commit_group;" ::: "memory")
#define CP_WAIT1()  asm volatile("cp.async.wait_group 1;" ::: "memory")

__device__ __forceinline__ uint32_t pack_bf16x2(float lo_f, float hi_f) {
    __nv_bfloat162 p(__float2bfloat16(lo_f), __float2bfloat16(hi_f));
    return *reinterpret_cast<uint32_t*>(&p);
}

__device__ __forceinline__ void split4(float4 v, uint2& hv, uint2& lv) {
    float hx = __bfloat162float(__float2bfloat16(v.x));
    float hy = __bfloat162float(__float2bfloat16(v.y));
    float hz = __bfloat162float(__float2bfloat16(v.z));
    float hw = __bfloat162float(__float2bfloat16(v.w));
    hv.x = pack_bf16x2(v.x, v.y);
    hv.y = pack_bf16x2(v.z, v.w);
    lv.x = pack_bf16x2(v.x - hx, v.y - hy);
    lv.y = pack_bf16x2(v.z - hz, v.w - hw);
}

// SMEM stage: Ahi 0 (8K), Alo 8K, Bhi 16K (4K), Blo 20K; stage = 24KB, 3 stages
#define A8K 8192
#define STAGE 24576
#define NSTAGE 3

// compute one 32-K chunk on a 128x64 tile (warp = 64x16); 3 passes
__device__ __forceinline__ void compute_chunk(uint32_t st, float acc[4][2][4],
                                              int lane, int mw, int nw) {
    const uint32_t Ahi = st, Alo = st + A8K;
    const uint32_t Bhi = st + 2 * A8K, Blo = st + 2 * A8K + 4096;
    const int lrow = lane & 15;
    const uint32_t lhi = (uint32_t)(lane >> 4) * 16;

    #pragma unroll
    for (int ks = 0; ks < 2; ks++) {
        const uint32_t kc = (uint32_t)ks * 32 + lhi;
        uint32_t ah[4][4], al[4][4], bh[4], bl[4];

        #pragma unroll
        for (int mt = 0; mt < 4; mt++) {
            uint32_t R = (uint32_t)(mw * 64 + mt * 16 + lrow) * 64;
            uint32_t off = R + (kc ^ ((R >> 3) & 0x30));
            ldsm4(ah[mt], Ahi + off);
            ldsm4(al[mt], Alo + off);
        }
        {
            uint32_t R = (uint32_t)(nw * 16 + lrow) * 64;
            uint32_t off = R + (kc ^ ((R >> 3) & 0x30));
            ldsm4(bh, Bhi + off);
            ldsm4(bl, Blo + off);
        }

        #pragma unroll
        for (int mt = 0; mt < 4; mt++)
            #pragma unroll
            for (int nt = 0; nt < 2; nt++)
                mma_bf16(acc[mt][nt], ah[mt], bh[nt], bh[nt + 2]);
        #pragma unroll
        for (int mt = 0; mt < 4; mt++)
            #pragma unroll
            for (int nt = 0; nt < 2; nt++)
                mma_bf16(acc[mt][nt], ah[mt], bl[nt], bl[nt + 2]);
        #pragma unroll
        for (int mt = 0; mt < 4; mt++)
            #pragma unroll
            for (int nt = 0; nt < 2; nt++)
                mma_bf16(acc[mt][nt], al[mt], bh[nt], bh[nt + 2]);
    }
}

__device__ __forceinline__ float silu(float x) {
    return x / (1.0f + __expf(-x));
}

// ---------------- split kernel: fp32 -> bf16 hi/lo ----------------
__global__ void split_kernel(const float4* __restrict__ src,
                             uint2* __restrict__ hi, uint2* __restrict__ lo, long n4)
{
    for (long i = (long)blockIdx.x * blockDim.x + threadIdx.x; i < n4;
         i += (long)gridDim.x * blockDim.x) {
        uint2 h, l;
        split4(src[i], h, l);
        hi[i] = h;
        lo[i] = l;
    }
}

// ---------------- kernel 1: h = silu(x@Wg^T) * (x@Wu^T), fused ----------------
// CTA: 128 tokens x 32 h-cols. B-tile (64 rows) interleaves gate/up per 8 rows:
// warp nw's 16 B-rows = 8 gate cols + the matching 8 up cols.
__global__ __launch_bounds__(256, 2)
void moe_upgate_kernel()
{
    extern __shared__ char smem[];
    const uint32_t smem_b = smem_u32(smem);

    const int tid = threadIdx.x;
    const int lane = tid & 31, warp = tid >> 5;
    const int g = lane >> 2, tg = lane & 3;
    const int nw = warp & 3, mw = warp >> 2;

    const int e = blockIdx.z;
    const int m0 = blockIdx.y * 128;
    const int n0 = blockIdx.x * 32;        // h-col base (32 per CTA)

    const long arow0 = (long)e * TPE + m0;
    const long brow0 = (long)e * 2 * HIDDEN;

    auto issue_stage = [&](int s, int c) {
        const int k0 = c * 32;
        const uint32_t st = smem_b + (uint32_t)s * STAGE;
        // A: 128 rows x 64B (hi & lo): 2 ops each per thread
        #pragma unroll
        for (int it = 0; it < 2; it++) {
            int idx = it * 256 + tid;
            int row = idx >> 2, c16 = idx & 3;
            uint32_t off = sw((uint32_t)(row * 64 + c16 * 16));
            long acol = (long)k0 + c16 * 8;
            CP_ASYNC16(st + off, g_x_hi + (arow0 + row) * D_MODEL + acol);
            CP_ASYNC16(st + A8K + off, g_x_lo + (arow0 + row) * D_MODEL + acol);
        }
        // B: 64 rows x 64B (hi & lo): 1 op each per thread
        {
            int row = tid >> 2, c16 = tid & 3;
            uint32_t off = sw((uint32_t)(row * 64 + c16 * 16));
            long acol = (long)k0 + c16 * 8;
            int w = row >> 4, sgu = (row >> 3) & 1, rr = row & 7;
            long brow = brow0 + (sgu ? HIDDEN : 0) + n0 + w * 8 + rr;
            CP_ASYNC16(st + 2 * A8K + off, g_wug_hi + brow * D_MODEL + acol);
            CP_ASYNC16(st + 2 * A8K + 4096 + off, g_wug_lo + brow * D_MODEL + acol);
        }
        CP_COMMIT();
    };

    float acc[4][2][4];
    #pragma unroll
    for (int i = 0; i < 4; i++)
        #pragma unroll
        for (int j = 0; j < 2; j++)
            #pragma unroll
            for (int k = 0; k < 4; k++) acc[i][j][k] = 0.0f;

    const int NCH = D_MODEL / 32;   // 64
    issue_stage(0, 0);
    issue_stage(1, 1);

    for (int c = 0; c < NCH; c++) {
        CP_WAIT1();
        __syncthreads();
        if (c + 2 < NCH) issue_stage((c + 2) % NSTAGE, c + 2);
        else CP_COMMIT();
        compute_chunk(smem_b + (uint32_t)(c % NSTAGE) * STAGE, acc, lane, mw, nw);
    }

    // epilogue: nt=0 gate, nt=1 matching up (warp owns 8 h-cols)
    #pragma unroll
    for (int mt = 0; mt < 4; mt++) {
        long row0 = arow0 + mw * 64 + mt * 16 + g;
        int col = n0 + nw * 8 + tg * 2;
        float vx = silu(acc[mt][0][0]) * acc[mt][1][0];
        float vy = silu(acc[mt][0][1]) * acc[mt][1][1];
        float vz = silu(acc[mt][0][2]) * acc[mt][1][2];
        float vw = silu(acc[mt][0][3]) * acc[mt][1][3];
        float hx = __bfloat162float(__float2bfloat16(vx));
        float hy = __bfloat162float(__float2bfloat16(vy));
        float hz = __bfloat162float(__float2bfloat16(vz));
        float hw = __bfloat162float(__float2bfloat16(vw));
        *reinterpret_cast<uint32_t*>(g_h_hi + row0 * HIDDEN + col) = pack_bf16x2(vx, vy);
        *reinterpret_cast<uint32_t*>(g_h_lo + row0 * HIDDEN + col) = pack_bf16x2(vx - hx, vy - hy);
        *reinterpret_cast<uint32_t*>(g_h_hi + (row0 + 8) * HIDDEN + col) = pack_bf16x2(vz, vw);
        *reinterpret_cast<uint32_t*>(g_h_lo + (row0 + 8) * HIDDEN + col) = pack_bf16x2(vz - hz, vw - hw);
    }
}

// ---------------- kernel 2: out = h @ Wd^T ----------------
// CTA: 128 tokens x 64 out-cols (warp = 64x16).
__global__ __launch_bounds__(256, 2)
void moe_down_kernel(float* __restrict__ out)
{
    extern __shared__ char smem[];
    const uint32_t smem_b = smem_u32(smem);

    const int tid = threadIdx.x;
    const int lane = tid & 31, warp = tid >> 5;
    const int g = lane >> 2, tg = lane & 3;
    const int nw = warp & 3, mw = warp >> 2;

    const int e = blockIdx.z;
    const int m0 = blockIdx.y * 128;
    const int n0 = blockIdx.x * 64;

    const long arow0 = (long)e * TPE + m0;
    const long bcol0 = (long)e * HIDDEN;

    auto issue_stage = [&](int s, int c) {
        const int k0 = c * 32;
        const uint32_t st = smem_b + (uint32_t)s * STAGE;
        #pragma unroll
        for (int it = 0; it < 2; it++) {
            int idx = it * 256 + tid;
            int row = idx >> 2, c16 = idx & 3;
            uint32_t off = sw((uint32_t)(row * 64 + c16 * 16));
            long acol = (long)k0 + c16 * 8;
            CP_ASYNC16(st + off, g_h_hi + (arow0 + row) * HIDDEN + acol);
            CP_ASYNC16(st + A8K + off, g_h_lo + (arow0 + row) * HIDDEN + acol);
        }
        {
            int row = tid >> 2, c16 = tid & 3;
            uint32_t off = sw((uint32_t)(row * 64 + c16 * 16));
            long acol = (long)k0 + c16 * 8;
            long brow = (long)(n0 + row) * (NUM_EXPERTS * HIDDEN) + bcol0;
            CP_ASYNC16(st + 2 * A8K + off, g_wd_hi + brow + acol);
            CP_ASYNC16(st + 2 * A8K + 4096 + off, g_wd_lo + brow + acol);
        }
        CP_COMMIT();
    };

    float acc[4][2][4];
    #pragma unroll
    for (int i = 0; i < 4; i++)
        #pragma unroll
        for (int j = 0; j < 2; j++)
            #pragma unroll
            for (int k = 0; k < 4; k++) acc[i][j][k] = 0.0f;

    const int NCH = HIDDEN / 32;    // 32
    issue_stage(0, 0);
    issue_stage(1, 1);

    for (int c = 0; c < NCH; c++) {
        CP_WAIT1();
        __syncthreads();
        if (c + 2 < NCH) issue_stage((c + 2) % NSTAGE, c + 2);
        else CP_COMMIT();
        compute_chunk(smem_b + (uint32_t)(c % NSTAGE) * STAGE, acc, lane, mw, nw);
    }

    #pragma unroll
    for (int mt = 0; mt < 4; mt++) {
        long row0 = arow0 + mw * 64 + mt * 16 + g;
        #pragma unroll
        for (int nt = 0; nt < 2; nt++) {
            int col = n0 + nw * 16 + nt * 8 + tg * 2;
            float2 v0, v1;
            v0.x = acc[mt][nt][0]; v0.y = acc[mt][nt][1];
            v1.x = acc[mt][nt][2]; v1.y = acc[mt][nt][3];
            *reinterpret_cast<float2*>(out + row0 * D_MODEL + col) = v0;
            *reinterpret_cast<float2*>(out + (row0 + 8) * D_MODEL + col) = v1;
        }
    }
}

// ---------------- launch ----------------
extern "C" void kernel_launch(void* const* d_in, const int* in_sizes, int n_in,
                              void* d_out, int out_size)
{
    const float* x        = (const float*)d_in[0];  // [16384, 2048]
    const float* w_upgate = (const float*)d_in[1];  // [E*2H, D]
    const float* w_down   = (const float*)d_in[2];  // [D, E*H]
    float* out = (float*)d_out;

    cudaFuncSetAttribute(moe_upgate_kernel,
                         cudaFuncAttributeMaxDynamicSharedMemorySize, NSTAGE * STAGE);
    cudaFuncSetAttribute(moe_down_kernel,
                         cudaFuncAttributeMaxDynamicSharedMemorySize, NSTAGE * STAGE);

    __nv_bfloat16 *xh, *xl, *ugh, *ugl, *wdh, *wdl;
    cudaGetSymbolAddress((void**)&xh,  g_x_hi);
    cudaGetSymbolAddress((void**)&xl,  g_x_lo);
    cudaGetSymbolAddress((void**)&ugh, g_wug_hi);
    cudaGetSymbolAddress((void**)&ugl, g_wug_lo);
    cudaGetSymbolAddress((void**)&wdh, g_wd_hi);
    cudaGetSymbolAddress((void**)&wdl, g_wd_lo);

    {
        long n4x  = (long)TOTAL_TOKENS * D_MODEL / 4;
        long n4ug = (long)2 * NUM_EXPERTS * HIDDEN * D_MODEL / 4;
        long n4wd = (long)D_MODEL * NUM_EXPERTS * HIDDEN / 4;
        split_kernel<<<2048, 256>>>((const float4*)x, (uint2*)xh, (uint2*)xl, n4x);
        split_kernel<<<2048, 256>>>((const float4*)w_upgate, (uint2*)ugh, (uint2*)ugl, n4ug);
        split_kernel<<<2048, 256>>>((const float4*)w_down, (uint2*)wdh, (uint2*)wdl, n4wd);
    }

    {
        dim3 grid(HIDDEN / 32, TPE / 128, NUM_EXPERTS);   // (32,16,8)
        moe_upgate_kernel<<<grid, 256, NSTAGE * STAGE>>>();
    }
    {
        dim3 grid(D_MODEL / 64, TPE / 128, NUM_EXPERTS);  // (32,16,8)
        moe_down_kernel<<<grid, 256, NSTAGE * STAGE>>>(out);
    }
}